// round 17
// baseline (speedup 1.0000x reference)
#include <cuda_runtime.h>
#include <cuda_fp16.h>
#include <math.h>

#define NPT   8192
#define CC    128
#define PP    1024
#define KMAX  64
#define NPAIR (NPT/2)
#define GRID_MAIN 296

// ---- main kernel dynamic smem layout (byte offsets) ----
// A (fp16 MMA operand, swizzled 128x256B) overlaid by eS (fp16 alphas) after MMA.
// VD holds (V + delta) fp16. redS dedicated. All per-iteration regions are
// HALF-PRIVATE by row block (rows [0,64) = half 0, [64,128) = half 1).
#define OFF_A     0
#define OFF_B     32768
#define OFF_VD    65536
#define OFF_REL   98304
#define OFF_IDX   102400
#define OFF_WPF   102912
#define OFF_BP    105984
#define OFF_SA    106496
#define OFF_BA    107008
#define OFF_RED   107648
#define DYN_SIZE  111744

// gemm3 dynamic smem (padded layout)
#define ASTR_B   272
#define G3_OFF_A 0
#define G3_OFF_W 17408
#define G3_DYN   52224

// scratch (device globals; zero-initialized at load; no allocations allowed)
__device__ float2 g_AV[NPT*CC];     // .x = x@w_src (Asrc), .y = x@w_lin (V)
__device__ float  g_Adst[NPT*CC];
__device__ int    g_idx[NPT*KMAX];
__device__ int    g_cnt[NPT];

// ---------------------------------------------------------------------------
__device__ __forceinline__ unsigned smem_u32(const void* p) {
    unsigned a;
    asm("{ .reg .u64 t; cvta.to.shared.u64 t, %1; cvt.u32.u64 %0, t; }" : "=r"(a) : "l"(p));
    return a;
}

__device__ __forceinline__ void ldsm4(unsigned* r, unsigned addr) {
    asm volatile("ldmatrix.sync.aligned.m8n8.x4.shared.b16 {%0,%1,%2,%3}, [%4];"
        : "=r"(r[0]), "=r"(r[1]), "=r"(r[2]), "=r"(r[3]) : "r"(addr));
}

__device__ __forceinline__ void mma16816(float* d, const unsigned* a, unsigned b0, unsigned b1) {
    asm volatile("mma.sync.aligned.m16n8k16.row.col.f32.f16.f16.f32 "
        "{%0,%1,%2,%3}, {%4,%5,%6,%7}, {%8,%9}, {%0,%1,%2,%3};"
        : "+f"(d[0]), "+f"(d[1]), "+f"(d[2]), "+f"(d[3])
        : "r"(a[0]), "r"(a[1]), "r"(a[2]), "r"(a[3]), "r"(b0), "r"(b1));
}

__device__ __forceinline__ float ex2f(float x) {
    float y;
    asm("ex2.approx.ftz.f32 %0, %1;" : "=f"(y) : "f"(x));
    return y;
}

// per-half barrier: 128 threads, barrier id 1 or 2
__device__ __forceinline__ void barh(int h) {
    asm volatile("bar.sync %0, %1;" :: "r"(h + 1), "r"(128) : "memory");
}

// fp16 tile addressing: 128 ch per 256B row, 16B-unit XOR swizzle.
__device__ __forceinline__ int haddr(int row, int ch) {
    return (row << 8) + ((((ch >> 3) ^ (row & 7)) & 15) << 4) + ((ch & 7) << 1);
}

// ---------------------------------------------------------------------------
// Kernel A: three GEMMs via HMMA, fp16 W transpose done inline in smem.
// mat0 (w_lin) -> g_AV.y, mat1 (w_src) -> g_AV.x, mat2 (w_dst) -> g_Adst.
// ---------------------------------------------------------------------------
__global__ __launch_bounds__(128)
void gemm3_tc_kernel(const float* __restrict__ x,
                     const float* __restrict__ wl,
                     const float* __restrict__ ws,
                     const float* __restrict__ wd)
{
    extern __shared__ __align__(16) char smem[];
    const unsigned sb = smem_u32(smem);
    const int t    = threadIdx.x;
    const int w    = t >> 5;
    const int lane = t & 31;
    const int row0 = blockIdx.x * 64;

    for (int q = t; q < 64 * CC; q += 128) {
        int row = q >> 7, c = q & 127;
        *(__half*)(smem + G3_OFF_A + row * ASTR_B + c * 2) =
            __float2half_rn(x[(size_t)(row0 + row) * CC + c]);
    }

    const unsigned aBase = sb + G3_OFF_A +
        (unsigned)((w * 16 + (lane & 15)) * ASTR_B + ((lane >> 4) << 4));
    const unsigned bBase = sb + G3_OFF_W +
        (unsigned)((((lane >> 4) << 3) + (lane & 7)) * ASTR_B + (((lane >> 3) & 1) << 4));

    for (int mat = 0; mat < 3; mat++) {
        // inline BT[n][k] = W[k*128+n] fp16 (coalesced float reads)
        const float* Wsrc = (mat == 0) ? wl : (mat == 1) ? ws : wd;
        for (int q = t; q < CC * CC; q += 128) {
            int k = q >> 7, n = q & 127;
            *(__half*)(smem + G3_OFF_W + n * ASTR_B + k * 2) = __float2half_rn(Wsrc[q]);
        }
        __syncthreads();

        float acc[16][4];
        #pragma unroll
        for (int nt = 0; nt < 16; nt++) {
            acc[nt][0] = 0.f; acc[nt][1] = 0.f; acc[nt][2] = 0.f; acc[nt][3] = 0.f;
        }
        #pragma unroll
        for (int kk = 0; kk < 8; kk++) {
            unsigned afr[4];
            ldsm4(afr, aBase + kk * 32);
            #pragma unroll
            for (int pp = 0; pp < 8; pp++) {
                unsigned bfr[4];
                ldsm4(bfr, bBase + (unsigned)(pp * 16 * ASTR_B) + kk * 32);
                mma16816(acc[2 * pp],     afr, bfr[0], bfr[1]);
                mma16816(acc[2 * pp + 1], afr, bfr[2], bfr[3]);
            }
        }

        int r0 = w * 16 + (lane >> 2);
        int c0 = 2 * (lane & 3);
        if (mat == 2) {
            #pragma unroll
            for (int nt = 0; nt < 16; nt++) {
                int col = nt * 8 + c0;
                *(float2*)&g_Adst[(size_t)(row0 + r0) * CC + col] =
                    make_float2(acc[nt][0], acc[nt][1]);
                *(float2*)&g_Adst[(size_t)(row0 + r0 + 8) * CC + col] =
                    make_float2(acc[nt][2], acc[nt][3]);
            }
        } else if (mat == 0) {
            #pragma unroll
            for (int nt = 0; nt < 16; nt++) {
                int col = nt * 8 + c0;
                size_t b0i = (size_t)(row0 + r0) * CC + col;
                size_t b1i = (size_t)(row0 + r0 + 8) * CC + col;
                g_AV[b0i].y     = acc[nt][0];
                g_AV[b0i + 1].y = acc[nt][1];
                g_AV[b1i].y     = acc[nt][2];
                g_AV[b1i + 1].y = acc[nt][3];
            }
        } else {
            #pragma unroll
            for (int nt = 0; nt < 16; nt++) {
                int col = nt * 8 + c0;
                size_t b0i = (size_t)(row0 + r0) * CC + col;
                size_t b1i = (size_t)(row0 + r0 + 8) * CC + col;
                g_AV[b0i].x     = acc[nt][0];
                g_AV[b0i + 1].x = acc[nt][1];
                g_AV[b1i].x     = acc[nt][2];
                g_AV[b1i + 1].x = acc[nt][3];
            }
        }
        __syncthreads();
    }
}

// ---------------------------------------------------------------------------
// Kernel B: radius + nearest-K selection, WARP-PER-TARGET (no block barriers
// after the cloud stage; ballot/popc ordered compaction, d2 cached in regs).
// ---------------------------------------------------------------------------
__global__ __launch_bounds__(256)
void neigh_kernel(const float* __restrict__ pos)
{
    __shared__ float pos_s[PP * 3];
    const int t     = threadIdx.x;
    const int lane  = t & 31;
    const int wi    = t >> 5;
    const int i0    = blockIdx.x * 8;
    const int cbase = (i0 >> 10) << 10;

    for (int idx = t; idx < PP * 3; idx += 256)
        pos_s[idx] = pos[cbase * 3 + idx];
    __syncthreads();

    const int i  = i0 + wi;
    const int li = i - cbase;
    const float px = pos_s[li * 3 + 0];
    const float py = pos_s[li * 3 + 1];
    const float pz = pos_s[li * 3 + 2];
    const unsigned R2b = __float_as_uint(0.04f);

    unsigned bits[32];
    int cnt = 0;
    #pragma unroll
    for (int q = 0; q < 32; q++) {
        int j = q * 32 + lane;
        float dx = px - pos_s[j * 3 + 0];
        float dy = py - pos_s[j * 3 + 1];
        float dz = pz - pos_s[j * 3 + 2];
        unsigned b = __float_as_uint(dx * dx + dy * dy + dz * dz);
        bits[q] = b;   // >=0 floats: bit order == value order
        cnt += __popc(__ballot_sync(0xffffffffu, b <= R2b));
    }

    unsigned th = R2b;
    if (cnt > KMAX) {
        // rare: bit-level binary search for the KMAX-th smallest distance
        unsigned lo = 0, hi = R2b;
        while (lo < hi) {
            unsigned mid = lo + ((hi - lo) >> 1);
            int c2 = 0;
            #pragma unroll
            for (int q = 0; q < 32; q++)
                c2 += __popc(__ballot_sync(0xffffffffu, bits[q] <= mid));
            if (c2 >= KMAX) hi = mid; else lo = mid + 1;
        }
        th = lo;
    }

    // ordered compaction (ascending j)
    int base = 0;
    #pragma unroll
    for (int q = 0; q < 32; q++) {
        bool sel = (bits[q] <= th);
        unsigned ball = __ballot_sync(0xffffffffu, sel);
        int rank = base + __popc(ball & ((1u << lane) - 1u));
        if (sel && rank < KMAX) g_idx[i * KMAX + rank] = q * 32 + lane;
        base += __popc(ball);
    }
    if (lane == 0) g_cnt[i] = (base < KMAX) ? base : KMAX;
}

// ---------------------------------------------------------------------------
// Kernel C: HMMA fused attention. Persistent, 2 targets/iter, TWO independent
// half-CTA pipelines with named barriers + cross-iteration g_idx prefetch.
// ---------------------------------------------------------------------------
__global__ __launch_bounds__(256, 2)
void main_tc_kernel(const float* __restrict__ pos,
                    const float* __restrict__ nrm,
                    const float* __restrict__ w_pos,
                    const float* __restrict__ b_pos,
                    const float* __restrict__ pos_gamma,
                    const float* __restrict__ pos_beta,
                    const float* __restrict__ pos_mean,
                    const float* __restrict__ pos_var,
                    const float* __restrict__ w_attn,
                    const float* __restrict__ b_attn,
                    const float* __restrict__ attn_gamma,
                    const float* __restrict__ attn_beta,
                    const float* __restrict__ attn_mean,
                    const float* __restrict__ attn_var,
                    float* __restrict__ out)
{
    extern __shared__ __align__(16) char smem[];
    const unsigned sb = smem_u32(smem);

    const int t    = threadIdx.x;
    const int w    = t >> 5;
    const int lane = t & 31;
    const int hh   = t >> 7;      // half index (0/1) == target index within pair
    const int ht   = t & 127;     // thread id within half

    float* relS = (float*)(smem + OFF_REL);
    float* redS = (float*)(smem + OFF_RED);   // dedicated (NOT overlaid)
    int*   idxS = (int*)  (smem + OFF_IDX);   // premultiplied: gj * 128
    float* wpfS = (float*)(smem + OFF_WPF);
    float* bpS  = (float*)(smem + OFF_BP);
    float* saS  = (float*)(smem + OFF_SA);    // pre-scaled by log2(e)
    float* baS  = (float*)(smem + OFF_BA);    // pre-scaled by log2(e)

    // per-channel folded-BN constants
    if (t < 128) {
        int c = t;
        float sp = rsqrtf(pos_var[c] + 1e-5f) * pos_gamma[c];
        bpS[c] = (b_pos[c] - pos_mean[c]) * sp + pos_beta[c];
        #pragma unroll
        for (int r = 0; r < 6; r++) wpfS[r * 128 + c] = w_pos[r * 128 + c] * sp;
        const float L2E = 1.4426950408889634f;
        float sa = rsqrtf(attn_var[c] + 1e-5f) * attn_gamma[c];
        saS[c] = sa * L2E;
        baS[c] = ((b_attn[c] - attn_mean[c]) * sa + attn_beta[c]) * L2E;
    }

    // B[n][k] = w_attn[k][n] fp16 into swizzled tile (once per CTA)
    for (int q = t; q < 128 * 128; q += 256) {
        int n = q & 127, k = q >> 7;
        *(__half*)(smem + OFF_B + haddr(n, k)) = __float2half_rn(w_attn[k * 128 + n]);
    }
    __syncthreads();

    const int kk   = ht & 63;
    const int part = ht >> 6;

    // prime the cross-iteration g_idx prefetch
    int next_jj = g_idx[(2 * (int)blockIdx.x + hh) * KMAX + kk];

    for (int p = blockIdx.x; p < NPAIR; p += GRID_MAIN) {
        const int i0 = 2 * p;
        const int i  = i0 + hh;          // this half's target
        const int cb = (i >> 10) << 10;

        // issue iteration's global reads BEFORE the barrier (read-only, safe)
        const int mt = g_cnt[i];
        const int gj = cb + next_jj;
        const int k2 = hh * 64 + kk;
        float v0, v1, v2;
        int   idxv = gj * CC;
        if (part == 0) {
            v0 = pos[i * 3 + 0] - pos[gj * 3 + 0];
            v1 = pos[i * 3 + 1] - pos[gj * 3 + 1];
            v2 = pos[i * 3 + 2] - pos[gj * 3 + 2];
        } else {
            v0 = nrm[i * 3 + 0] - nrm[gj * 3 + 0];
            v1 = nrm[i * 3 + 1] - nrm[gj * 3 + 1];
            v2 = nrm[i * 3 + 2] - nrm[gj * 3 + 2];
        }

        barh(hh);   // prev-iter epilogue reads of this half's regions done

        if (part == 0) {
            idxS[k2] = idxv;
            relS[k2 * 8 + 0] = v0;
            relS[k2 * 8 + 1] = v1;
            relS[k2 * 8 + 2] = v2;
        } else {
            relS[k2 * 8 + 3] = v0;
            relS[k2 * 8 + 4] = v1;
            relS[k2 * 8 + 5] = v2;
        }
        barh(hh);

        // --- build A (fp16, swizzled) + vdS = V + delta (fp16); one LDG.64/k ---
        {
            int c   = ht;                 // one channel per thread in this half
            int tb  = hh * 64;
            float ad = g_Adst[i * CC + c];
            float bp = bpS[c];
            float wp0 = wpfS[0 * 128 + c], wp1 = wpfS[1 * 128 + c], wp2 = wpfS[2 * 128 + c];
            float wp3 = wpfS[3 * 128 + c], wp4 = wpfS[4 * 128 + c], wp5 = wpfS[5 * 128 + c];

            float2 buf[8];
            #pragma unroll
            for (int kp = 0; kp < 8; kp++)
                buf[kp] = (kp < mt) ? g_AV[idxS[tb + kp] + c] : make_float2(0.f, 0.f);

            int k = 0;
            #define A_BODY(KK, AV) do {                                           \
                const float4 ra = *(const float4*)&relS[(tb + (KK)) * 8];         \
                const float4 rb = *(const float4*)&relS[(tb + (KK)) * 8 + 4];     \
                float d = bp;                                                     \
                d = fmaf(ra.x, wp0, d); d = fmaf(ra.y, wp1, d);                   \
                d = fmaf(ra.z, wp2, d); d = fmaf(ra.w, wp3, d);                   \
                d = fmaf(rb.x, wp4, d); d = fmaf(rb.y, wp5, d);                   \
                d = fmaxf(d, 0.f);                                                \
                int ha = haddr(tb + (KK), c);                                     \
                *(__half*)(smem + OFF_VD + ha) = __float2half_rn((AV).y + d);     \
                *(__half*)(smem + OFF_A + ha) = __float2half_rn(ad - (AV).x + d); \
            } while (0)

            for (; k + 8 <= mt; k += 8) {
                #pragma unroll
                for (int j = 0; j < 8; j++) {
                    float2 av = buf[j];
                    buf[j] = (k + 8 + j < mt) ? g_AV[idxS[tb + k + 8 + j] + c]
                                              : make_float2(0.f, 0.f);
                    A_BODY(k + j, av);
                }
            }
            #pragma unroll
            for (int j = 0; j < 8; j++)
                if (k + j < mt) A_BODY(k + j, buf[j]);
            #undef A_BODY
        }
        barh(hh);

        // --- HMMA: warp w -> rows [w*16, w*16+16) x 128 couts; skip empty warps.
        const bool wactive = ((w & 3) * 16) < mt;

        if (wactive) {
            float acc[16][4];
            #pragma unroll
            for (int nt = 0; nt < 16; nt++) {
                acc[nt][0] = 0.f; acc[nt][1] = 0.f; acc[nt][2] = 0.f; acc[nt][3] = 0.f;
            }
            const int r    = w * 16 + (lane & 15);
            const int u0a  = lane >> 4;
            const int xr   = lane & 7;
            const unsigned aRow = sb + OFF_A + (unsigned)(r << 8);
            const int nrow0 = ((lane >> 4) << 3) + (lane & 7);
            const int u0b  = (lane >> 3) & 1;
            const unsigned bRow = sb + OFF_B + (unsigned)(nrow0 << 8);

            #pragma unroll
            for (int kx = 0; kx < 8; kx++) {
                unsigned afr[4];
                ldsm4(afr, aRow + (unsigned)((((kx * 2 + u0a) ^ xr) & 15) << 4));
                #pragma unroll
                for (int pp = 0; pp < 8; pp++) {
                    unsigned bfr[4];
                    ldsm4(bfr, bRow + (unsigned)(pp << 12)
                               + (unsigned)((((kx * 2 + u0b) ^ xr) & 15) << 4));
                    mma16816(acc[2 * pp],     afr, bfr[0], bfr[1]);
                    mma16816(acc[2 * pp + 1], afr, bfr[2], bfr[3]);
                }
            }

            // store alphas (pre-affine) fp16 into eS (overlay of this warp's A rows)
            int r0 = w * 16 + (lane >> 2);
            int c0 = 2 * (lane & 3);
            #pragma unroll
            for (int nt = 0; nt < 16; nt++) {
                int c = nt * 8 + c0;
                *(__half2*)(smem + OFF_A + haddr(r0, c)) =
                    __floats2half2_rn(acc[nt][0], acc[nt][1]);
                *(__half2*)(smem + OFF_A + haddr(r0 + 8, c)) =
                    __floats2half2_rn(acc[nt][2], acc[nt][3]);
            }
        }
        barh(hh);

        // --- epilogue (pure smem, per half): thread = (cp-pair, k-half) ---
        {
            const int half  = (ht >> 6) & 1;
            const int cpp   = ht & 63;
            const int cp    = cpp * 2;
            const int ibase = hh * 64;
            const int khalf = (mt + 1) >> 1;
            const int kb    = half ? khalf : 0;
            const int ke    = half ? mt : khalf;
            const float2 sa2 = *(const float2*)&saS[cp];
            const float2 ba2 = *(const float2*)&baS[cp];

            float fs0 = 0.f, fs1 = 0.f, fa0 = 0.f, fa1 = 0.f;

            #define E2_BODY(KK) do {                                              \
                int ha = haddr(ibase + (KK), cp);                                 \
                float2 ar = __half22float2(*(const __half2*)(smem + OFF_A + ha)); \
                float2 vd = __half22float2(*(const __half2*)(smem + OFF_VD + ha)); \
                float a0 = fmaxf(fmaf(ar.x, sa2.x, ba2.x), 0.f);                  \
                float a1 = fmaxf(fmaf(ar.y, sa2.y, ba2.y), 0.f);                  \
                float e0 = ex2f(a0);                                              \
                float e1 = ex2f(a1);                                              \
                fs0 += e0; fs1 += e1;                                             \
                fa0 = fmaf(e0, vd.x, fa0);                                        \
                fa1 = fmaf(e1, vd.y, fa1);                                        \
            } while (0)

            int k = kb;
            for (; k + 4 <= ke; k += 4) {
                E2_BODY(k); E2_BODY(k + 1); E2_BODY(k + 2); E2_BODY(k + 3);
            }
            for (; k < ke; k++) E2_BODY(k);
            #undef E2_BODY

            *(float4*)&redS[(((half << 1) | hh) * 64 + cpp) * 4] =
                make_float4(fs0, fs1, fa0, fa1);
        }

        // cross-iteration prefetch of next g_idx (overlaps final + barrier)
        if (p + GRID_MAIN < NPAIR)
            next_jj = g_idx[(i + 2 * GRID_MAIN) * KMAX + kk];

        barh(hh);

        // --- final (per half): merge the two k-halves, normalize, write out ---
        {
            int cp2 = ht;
            int cq  = cp2 >> 1, s = cp2 & 1;
            const float* r0 = &redS[(hh * 64 + cq) * 4];
            const float* r1 = &redS[((2 + hh) * 64 + cq) * 4];
            float fs = r0[s] + r1[s];
            float fa = r0[2 + s] + r1[2 + s];
            out[(size_t)i * CC + cp2] = fa / fs;
        }
    }
}

// ---------------------------------------------------------------------------
extern "C" void kernel_launch(void* const* d_in, const int* in_sizes, int n_in,
                              void* d_out, int out_size)
{
    const float* x      = (const float*)d_in[0];
    const float* pos    = (const float*)d_in[1];
    const float* nrm    = (const float*)d_in[2];
    // d_in[3] = batch (structured, unused)
    const float* w_lin  = (const float*)d_in[4];
    const float* w_src  = (const float*)d_in[5];
    const float* w_dst  = (const float*)d_in[6];
    const float* w_pos  = (const float*)d_in[7];
    const float* b_pos  = (const float*)d_in[8];
    const float* pos_g  = (const float*)d_in[9];
    const float* pos_b  = (const float*)d_in[10];
    const float* pos_m  = (const float*)d_in[11];
    const float* pos_v  = (const float*)d_in[12];
    const float* w_attn = (const float*)d_in[13];
    const float* b_attn = (const float*)d_in[14];
    const float* attn_g = (const float*)d_in[15];
    const float* attn_b = (const float*)d_in[16];
    const float* attn_m = (const float*)d_in[17];
    const float* attn_v = (const float*)d_in[18];
    float* out = (float*)d_out;

    cudaFuncSetAttribute(main_tc_kernel,
                         cudaFuncAttributeMaxDynamicSharedMemorySize, DYN_SIZE);
    cudaFuncSetAttribute(gemm3_tc_kernel,
                         cudaFuncAttributeMaxDynamicSharedMemorySize, G3_DYN);

    gemm3_tc_kernel<<<128, 128, G3_DYN>>>(x, w_lin, w_src, w_dst);
    neigh_kernel<<<NPT / 8, 256>>>(pos);
    main_tc_kernel<<<GRID_MAIN, 256, DYN_SIZE>>>(
        pos, nrm, w_pos, b_pos, pos_g, pos_b, pos_m, pos_v,
        w_attn, b_attn, attn_g, attn_b, attn_m, attn_v, out);
}